// round 11
// baseline (speedup 1.0000x reference)
#include <cuda_runtime.h>

// Problem: B=32, T=256, D=64.
// real, imag: [B, T, D] float32.
// out: [2, T, B, D, D] float32.
//   out_real[t,b,p,q] = r_p*r_q + i_p*i_q
//   out_imag[t,b,p,q] = i_p*r_q - r_p*i_q
// where r = real[b, t, :], i = imag[b, t, :].
//
// Design (settled over R1-R9; this round: 2 tiles per CTA):
//  - Pure HBM-write-bound: 256MiB compulsory output, 0.75 flop/byte.
//    39.4us = 6.8TB/s effective (85% of spec).
//  - 512-thread CTA covers TWO consecutive (t,b) tiles of one component
//    = ONE contiguous 32KiB write stream; 4 streams/SM instead of 8 ->
//    longer sequential DRAM runs, fewer page breaks.
//  - __stcs (evict-first): keeps the write-once stream out of L2 (default
//    policy cost +5.7us, measured R8).
//  - q-index is j-invariant -> rq/iq hoisted as one LDS.128 pair.

#define PB 32
#define PT 256
#define PD 64
#define TILE (PD * PD)            // 4096 floats per (t,b) per component
#define NTB  (PT * PB)            // 8192 tiles per component
#define IMAG_OFF ((size_t)NTB * TILE)

__global__ __launch_bounds__(512, 4)
void qouterc_kernel(const float* __restrict__ real,
                    const float* __restrict__ imag,
                    float* __restrict__ out)
{
    // grid = NTB (8192). bid -> (comp, tile-pair u): each CTA writes tiles
    // tb = 2u and 2u+1 of component comp as one contiguous 32KiB run.
    const int bid  = blockIdx.x;
    const int comp = bid >> 12;           // 0 = real, 1 = imag (NTB/2 = 4096 pairs)
    const int u    = bid & 4095;          // tile-pair index

    const int tid  = threadIdx.x;
    const int half = tid >> 8;            // 0 -> tb = 2u, 1 -> tb = 2u+1
    const int lt   = tid & 255;           // lane within half (0..255)

    const int tb = 2 * u + half;          // tb = t*B + b (matches out layout)
    const int t  = tb >> 5;
    const int b  = tb & 31;

    // Two tiles' vectors: [half][D]
    __shared__ __align__(16) float rs[2][PD];
    __shared__ __align__(16) float is[2][PD];

    // Input layout [B, T, D]: element (b, t, d) at b*T*D + t*D + d.
    // Each half's first 128 threads load that half's r/i vectors.
    const size_t in_base = (size_t)b * (PT * PD) + (size_t)t * PD;
    if (lt < PD)
        rs[half][lt] = real[in_base + lt];
    else if (lt < 2 * PD)
        is[half][lt - PD] = imag[in_base + (lt - PD)];
    __syncthreads();

    // Per-half mapping identical to the proven R9 kernel:
    // n4 = j*256 + lt, p = j*16 + (lt>>4), q = (lt&15)<<2 (j-invariant).
    const int q  = (lt & 15) << 2;
    const int p0 = lt >> 4;

    const float4 rq4 = *reinterpret_cast<const float4*>(&rs[half][q]);
    const float4 iq4 = *reinterpret_cast<const float4*>(&is[half][q]);

    float* out_t = out + (size_t)comp * IMAG_OFF + (size_t)tb * TILE;

    #pragma unroll
    for (int j = 0; j < 4; ++j) {
        const int p  = j * 16 + p0;          // row
        const int n4 = j * 256 + lt;         // float4 index within tile

        const float rp = rs[half][p];        // broadcast LDS (conflict-free)
        const float ip = is[half][p];

        float4 v;
        if (comp == 0) {
            v.x = rp * rq4.x + ip * iq4.x;
            v.y = rp * rq4.y + ip * iq4.y;
            v.z = rp * rq4.z + ip * iq4.z;
            v.w = rp * rq4.w + ip * iq4.w;
        } else {
            v.x = ip * rq4.x - rp * iq4.x;
            v.y = ip * rq4.y - rp * iq4.y;
            v.z = ip * rq4.z - rp * iq4.z;
            v.w = ip * rq4.w - rp * iq4.w;
        }

        // Streaming store: write-once output, evict-first in L2.
        __stcs(reinterpret_cast<float4*>(out_t) + n4, v);
    }
}

extern "C" void kernel_launch(void* const* d_in, const int* in_sizes, int n_in,
                              void* d_out, int out_size)
{
    const float* real = (const float*)d_in[0];
    const float* imag = (const float*)d_in[1];
    float* out = (float*)d_out;

    // 2 components x 4096 tile-pairs; 512 threads each.
    qouterc_kernel<<<NTB, 512>>>(real, imag, out);
}